// round 6
// baseline (speedup 1.0000x reference)
#include <cuda_runtime.h>
#include <cuda_bf16.h>

// Problem constants (fixed by the dataset)
#define N_NODES 30000
#define N_EDGES 480000
#define T_STEPS 8
#define F_IN 8
#define HID 32
#define KCHEB 5
#define PERIODS 8

// ---------------------------------------------------------------------------
// Scratch (device globals; allocation-free rule)
// ---------------------------------------------------------------------------
__device__ float g_deg[N_NODES];
__device__ float g_dis[N_NODES];
__device__ int   g_rowcnt[N_NODES];
__device__ int   g_rowptr[N_NODES + 1];
__device__ int   g_rowfill[N_NODES];
__device__ int   g_col[N_EDGES];
__device__ float g_ew[N_EDGES];

// Chebyshev polys of X: [k][n][t*8+f], k=0..4, C=64
__device__ float g_TxX[5][N_NODES * 64];
// Chebyshev polys of H for k=1..4: [k-1][n][c], C=32
__device__ float g_TxH[4][N_NODES * 32];
__device__ float g_H[N_NODES * 32];
__device__ float g_C[N_NODES * 32];
__device__ float g_Z[N_NODES * 128];       // gate pre-activations [n][4*32]
__device__ float g_WBt[128 * 200];         // packed weights, [gate-out gh][k-dim kk]

// ---------------------------------------------------------------------------
// Prep kernels
// ---------------------------------------------------------------------------
__global__ void zero_prep_kernel() {
    int n = blockIdx.x * blockDim.x + threadIdx.x;
    if (n < N_NODES) { g_deg[n] = 0.f; g_rowcnt[n] = 0; }
}

__global__ void hist_kernel(const int* __restrict__ ei) {
    int e = blockIdx.x * blockDim.x + threadIdx.x;
    if (e >= N_EDGES) return;
    int s = ei[e], d = ei[N_EDGES + e];
    if (s != d) {
        atomicAdd(&g_deg[s], 1.f);
        atomicAdd(&g_rowcnt[d], 1);
    }
}

__global__ void dis_kernel() {
    int n = blockIdx.x * blockDim.x + threadIdx.x;
    if (n < N_NODES) {
        float dg = g_deg[n];
        g_dis[n] = (dg > 0.f) ? rsqrtf(dg) : 0.f;
    }
}

// Single-block exclusive scan of rowcnt -> rowptr (and rowfill copy)
__global__ void scan_kernel() {
    __shared__ int sums[1024];
    int t = threadIdx.x;
    const int IT = 30;  // 1024*30 >= 30000
    int base = t * IT;
    int s = 0;
    for (int i = 0; i < IT; i++) {
        int idx = base + i;
        if (idx < N_NODES) s += g_rowcnt[idx];
    }
    sums[t] = s;
    __syncthreads();
    for (int d = 1; d < 1024; d <<= 1) {
        int v = (t >= d) ? sums[t - d] : 0;
        __syncthreads();
        sums[t] += v;
        __syncthreads();
    }
    int run = sums[t] - s;  // exclusive
    for (int i = 0; i < IT; i++) {
        int idx = base + i;
        if (idx < N_NODES) {
            g_rowptr[idx] = run;
            g_rowfill[idx] = run;
            run += g_rowcnt[idx];
        }
    }
    if (t == 1023) g_rowptr[N_NODES] = sums[1023];
}

__global__ void csrfill_kernel(const int* __restrict__ ei) {
    int e = blockIdx.x * blockDim.x + threadIdx.x;
    if (e >= N_EDGES) return;
    int s = ei[e], d = ei[N_EDGES + e];
    if (s != d) {
        int pos = atomicAdd(&g_rowfill[d], 1);
        g_col[pos] = s;
        g_ew[pos] = g_dis[s] * g_dis[d];
    }
}

// Pack Wx[4][5][8][32], Wh[4][5][32][32] -> WBt[gh][kk], gh = g*32+h,
// kk<40: (k,f), kk>=40: (k,c)
__global__ void pack_wbt_kernel(const float* __restrict__ Wx,
                                const float* __restrict__ Wh) {
    int id = blockIdx.x * blockDim.x + threadIdx.x;
    if (id >= 128 * 200) return;
    int gh = id / 200, kk = id % 200;
    int g = gh >> 5, h = gh & 31;
    float w;
    if (kk < 40) {
        int k5 = kk >> 3, f = kk & 7;
        w = Wx[((g * 5 + k5) * 8 + f) * 32 + h];
    } else {
        int q = kk - 40;
        int k5 = q >> 5, c = q & 31;
        w = Wh[((g * 5 + k5) * 32 + c) * 32 + h];
    }
    g_WBt[gh * 200 + kk] = w;
}

// timesteps [T][N][F] -> TxX[0] as [N][T*F]
__global__ void xt_kernel(const float* __restrict__ ts) {
    int i = blockIdx.x * blockDim.x + threadIdx.x;
    if (i >= N_NODES * 64) return;
    int n = i >> 6, r = i & 63;
    int tt = r >> 3, f = r & 7;
    g_TxX[0][i] = ts[(tt * N_NODES + n) * 8 + f];
}

__global__ void zero_state_kernel() {
    int i = blockIdx.x * blockDim.x + threadIdx.x;
    if (i < N_NODES * 32) { g_H[i] = 0.f; g_C[i] = 0.f; }
}

// ---------------------------------------------------------------------------
// SpMM: out = alpha * lap(xin) - xprev, lap(x)[n] = -sum_{e in row n} w_e * x[col_e]
// Warp per dst node, lane = channel.
// ---------------------------------------------------------------------------
__global__ void spmm_x_kernel(int k) {
    int gtid = blockIdx.x * blockDim.x + threadIdx.x;
    int row = gtid >> 5, lane = gtid & 31;
    if (row >= N_NODES) return;
    const float* __restrict__ xin = g_TxX[k - 1];
    const float* __restrict__ xprev = (k >= 2) ? g_TxX[k - 2] : nullptr;
    float* __restrict__ xout = g_TxX[k];
    float alpha = (k >= 2) ? 2.f : 1.f;
    int e = g_rowptr[row], end = g_rowptr[row + 1];
    float a0 = 0.f, a1 = 0.f;
    for (; e + 1 < end; e += 2) {
        int s0 = g_col[e], s1 = g_col[e + 1];
        float w0 = g_ew[e], w1 = g_ew[e + 1];
        float x00 = xin[s0 * 64 + lane], x01 = xin[s0 * 64 + 32 + lane];
        float x10 = xin[s1 * 64 + lane], x11 = xin[s1 * 64 + 32 + lane];
        a0 = fmaf(w0, x00, a0); a0 = fmaf(w1, x10, a0);
        a1 = fmaf(w0, x01, a1); a1 = fmaf(w1, x11, a1);
    }
    if (e < end) {
        int s0 = g_col[e]; float w0 = g_ew[e];
        a0 = fmaf(w0, xin[s0 * 64 + lane], a0);
        a1 = fmaf(w0, xin[s0 * 64 + 32 + lane], a1);
    }
    float o0 = -alpha * a0, o1 = -alpha * a1;
    if (xprev) {
        o0 -= xprev[row * 64 + lane];
        o1 -= xprev[row * 64 + 32 + lane];
    }
    xout[row * 64 + lane] = o0;
    xout[row * 64 + 32 + lane] = o1;
}

__global__ void spmm_h_kernel(int k) {
    int gtid = blockIdx.x * blockDim.x + threadIdx.x;
    int row = gtid >> 5, lane = gtid & 31;
    if (row >= N_NODES) return;
    const float* __restrict__ xin = (k == 1) ? g_H : g_TxH[k - 2];
    const float* __restrict__ xprev = (k == 1) ? nullptr : ((k == 2) ? g_H : g_TxH[k - 3]);
    float* __restrict__ xout = g_TxH[k - 1];
    float alpha = (k == 1) ? 1.f : 2.f;
    int e = g_rowptr[row], end = g_rowptr[row + 1];
    float a0 = 0.f, a0b = 0.f;
    for (; e + 1 < end; e += 2) {
        int s0 = g_col[e], s1 = g_col[e + 1];
        float w0 = g_ew[e], w1 = g_ew[e + 1];
        a0  = fmaf(w0, xin[s0 * 32 + lane], a0);
        a0b = fmaf(w1, xin[s1 * 32 + lane], a0b);
    }
    if (e < end) {
        a0 = fmaf(g_ew[e], xin[g_col[e] * 32 + lane], a0);
    }
    float o0 = -alpha * (a0 + a0b);
    if (xprev) o0 -= xprev[row * 32 + lane];
    xout[row * 32 + lane] = o0;
}

// ---------------------------------------------------------------------------
// Gates GEMM: Z[n][128] = A(n,:,t) [200] @ WBt^T, where
//   A cols 0..39   = TxX[k][n][t*8+f]
//   A cols 40..71  = H[n][c]
//   A cols 72..199 = TxH[k-1][n][c]
// BM=64, BN=128, BK=8, 256 threads, 8x4 micro-tile, fma.rn.f32x2 k-paired.
// ---------------------------------------------------------------------------
#define FMA2(acc, a, b) \
    asm volatile("fma.rn.f32x2 %0, %1, %2, %0;" : "+l"(acc) : "l"(a), "l"(b))

__global__ __launch_bounds__(256) void gates_gemm_kernel(int t) {
    __shared__ __align__(16) float As[64 * 8];    // [m][k]
    __shared__ __align__(16) float Bs[128 * 12];  // [n][k], stride 12 (conflict-free)
    int tid = threadIdx.x;
    int cg = tid & 31, rg = tid >> 5;
    int m0 = blockIdx.x * 64;
    int t8 = t * 8;

    unsigned long long acc[8][4];
#pragma unroll
    for (int i = 0; i < 8; i++)
#pragma unroll
        for (int j = 0; j < 4; j++) acc[i][j] = 0ull;

    for (int k0 = 0; k0 < 200; k0 += 8) {
        // A tile: 512 elems, 2 per thread; consecutive threads write consecutive k
#pragma unroll
        for (int i = 0; i < 2; i++) {
            int l = tid + i * 256;
            int ml = l >> 3, kl = l & 7;
            int kk = k0 + kl, n = m0 + ml;
            float v = 0.f;
            if (n < N_NODES) {
                if (kk < 40) {
                    int k5 = kk >> 3, f = kk & 7;
                    v = g_TxX[k5][n * 64 + t8 + f];
                } else if (kk < 72) {
                    v = g_H[n * 32 + (kk - 40)];
                } else {
                    int q = kk - 72;
                    v = g_TxH[q >> 5][n * 32 + (q & 31)];
                }
            }
            As[ml * 8 + kl] = v;
        }
        // B tile: 1024 elems as float4
        {
            int nl = tid >> 1, kl4 = (tid & 1) * 4;
            float4 wv = *(const float4*)&g_WBt[nl * 200 + k0 + kl4];
            *(float4*)&Bs[nl * 12 + kl4] = wv;
        }
        __syncthreads();
#pragma unroll
        for (int kc = 0; kc < 8; kc += 4) {
            unsigned long long b0[4], b1[4];
#pragma unroll
            for (int j = 0; j < 4; j++) {
                ulonglong2 bv = *(const ulonglong2*)&Bs[(cg + 32 * j) * 12 + kc];
                b0[j] = bv.x; b1[j] = bv.y;
            }
#pragma unroll
            for (int i = 0; i < 8; i++) {
                ulonglong2 av = *(const ulonglong2*)&As[(rg * 8 + i) * 8 + kc];
#pragma unroll
                for (int j = 0; j < 4; j++) {
                    FMA2(acc[i][j], av.x, b0[j]);
                    FMA2(acc[i][j], av.y, b1[j]);
                }
            }
        }
        __syncthreads();
    }
#pragma unroll
    for (int i = 0; i < 8; i++) {
        int n = m0 + rg * 8 + i;
        if (n < N_NODES) {
#pragma unroll
            for (int j = 0; j < 4; j++) {
                union { unsigned long long u; float2 f; } cv;
                cv.u = acc[i][j];
                g_Z[n * 128 + cg + 32 * j] = cv.f.x + cv.f.y;
            }
        }
    }
}

// ---------------------------------------------------------------------------
// LSTM pointwise update
// ---------------------------------------------------------------------------
__device__ __forceinline__ float sigm(float x) {
    return 1.f / (1.f + __expf(-x));
}

__global__ void lstm_kernel(const float* __restrict__ w_c,
                            const float* __restrict__ b) {
    int g = blockIdx.x * blockDim.x + threadIdx.x;
    if (g >= N_NODES * 32) return;
    int n = g >> 5, h = g & 31;
    float zi = g_Z[n * 128 + h];
    float zf = g_Z[n * 128 + 32 + h];
    float zc = g_Z[n * 128 + 64 + h];
    float zo = g_Z[n * 128 + 96 + h];
    float c = g_C[g];
    float I  = sigm(zi + w_c[h] * c + b[h]);
    float Fg = sigm(zf + w_c[32 + h] * c + b[32 + h]);
    float T  = tanhf(zc + b[64 + h]);
    float cn = Fg * c + I * T;
    float O  = sigm(zo + w_c[64 + h] * cn + b[96 + h]);
    g_C[g] = cn;
    g_H[g] = O * tanhf(cn);
}

// ---------------------------------------------------------------------------
// Output head: out[n][p] = relu(H[n]) . W_lin[p] + b_lin[p]
// ---------------------------------------------------------------------------
__global__ void head_kernel(const float* __restrict__ Wl,
                            const float* __restrict__ bl,
                            float* __restrict__ out) {
    __shared__ float w[256];
    __shared__ float b[8];
    int tid = threadIdx.x;
    if (tid < 256) w[tid] = Wl[tid];
    if (tid < 8) b[tid] = bl[tid];
    __syncthreads();
    int n = blockIdx.x * blockDim.x + tid;
    if (n >= N_NODES) return;
    float h[32];
#pragma unroll
    for (int c = 0; c < 32; c++) {
        float v = g_H[n * 32 + c];
        h[c] = v > 0.f ? v : 0.f;
    }
#pragma unroll
    for (int p = 0; p < 8; p++) {
        float a = b[p];
#pragma unroll
        for (int c = 0; c < 32; c++) a = fmaf(h[c], w[p * 32 + c], a);
        out[n * 8 + p] = a;
    }
}

// ---------------------------------------------------------------------------
// kernel_launch
// ---------------------------------------------------------------------------
extern "C" void kernel_launch(void* const* d_in, const int* in_sizes, int n_in,
                              void* d_out, int out_size) {
    const float* timesteps = (const float*)d_in[0];
    const int*   edge_idx  = (const int*)d_in[1];
    const float* Wx        = (const float*)d_in[2];
    const float* Wh        = (const float*)d_in[3];
    const float* w_c       = (const float*)d_in[4];
    const float* b_gates   = (const float*)d_in[5];
    const float* W_lin     = (const float*)d_in[6];
    const float* b_lin     = (const float*)d_in[7];
    float* out = (float*)d_out;

    const int TB = 256;
    const int gN   = (N_NODES + TB - 1) / TB;
    const int gE   = (N_EDGES + TB - 1) / TB;
    const int gNC  = (N_NODES * 32 + TB - 1) / TB;
    const int gX   = (N_NODES * 64 + TB - 1) / TB;
    const int gSp  = (N_NODES * 32 + TB - 1) / TB;  // warp per node, 8 nodes/block
    const int gGm  = (N_NODES + 63) / 64;
    const int gPk  = (128 * 200 + TB - 1) / TB;

    // Graph structure + normalization
    zero_prep_kernel<<<gN, TB>>>();
    hist_kernel<<<gE, TB>>>(edge_idx);
    dis_kernel<<<gN, TB>>>();
    scan_kernel<<<1, 1024>>>();
    csrfill_kernel<<<gE, TB>>>(edge_idx);

    // Weight pack + X Chebyshev polys (all timesteps at once, C=64)
    pack_wbt_kernel<<<gPk, TB>>>(Wx, Wh);
    xt_kernel<<<gX, TB>>>(timesteps);
    for (int k = 1; k <= 4; k++) spmm_x_kernel<<<gSp, TB>>>(k);

    // LSTM state
    zero_state_kernel<<<gNC, TB>>>();

    for (int t = 0; t < T_STEPS; t++) {
        for (int k = 1; k <= 4; k++) spmm_h_kernel<<<gSp, TB>>>(k);
        gates_gemm_kernel<<<gGm, 256>>>(t);
        lstm_kernel<<<gNC, TB>>>(w_c, b_gates);
    }

    head_kernel<<<gN, TB>>>(W_lin, b_lin, out);
}

// round 7
// speedup vs baseline: 1.0038x; 1.0038x over previous
#include <cuda_runtime.h>
#include <cuda_bf16.h>

// Problem constants (fixed by the dataset)
#define N_NODES 30000
#define N_EDGES 480000
#define T_STEPS 8
#define F_IN 8
#define HID 32
#define KCHEB 5
#define PERIODS 8

// ---------------------------------------------------------------------------
// Scratch (device globals; allocation-free rule)
// ---------------------------------------------------------------------------
__device__ float g_deg[N_NODES];
__device__ float g_dis[N_NODES];
__device__ int   g_rowcnt[N_NODES];
__device__ int   g_rowptr[N_NODES + 1];
__device__ int   g_rowfill[N_NODES];
__device__ int   g_col[N_EDGES];
__device__ float g_ew[N_EDGES];

// Chebyshev polys of X: [k][n][t*8+f], k=0..4, C=64
__device__ float g_TxX[5][N_NODES * 64];
// Chebyshev polys of H for k=1..4: [k-1][n][c], C=32
__device__ float g_TxH[4][N_NODES * 32];
__device__ float g_H[N_NODES * 32];
__device__ float g_C[N_NODES * 32];
__device__ float g_Z[N_NODES * 128];       // gate pre-activations [n][4*32]
__device__ float g_WBt[128 * 200];         // packed weights, [gate-out gh][k-dim kk]

// ---------------------------------------------------------------------------
// Prep kernels
// ---------------------------------------------------------------------------
__global__ void zero_prep_kernel() {
    int n = blockIdx.x * blockDim.x + threadIdx.x;
    if (n < N_NODES) { g_deg[n] = 0.f; g_rowcnt[n] = 0; }
}

__global__ void hist_kernel(const int* __restrict__ ei) {
    int e = blockIdx.x * blockDim.x + threadIdx.x;
    if (e >= N_EDGES) return;
    int s = ei[e], d = ei[N_EDGES + e];
    if (s != d) {
        atomicAdd(&g_deg[s], 1.f);
        atomicAdd(&g_rowcnt[d], 1);
    }
}

__global__ void dis_kernel() {
    int n = blockIdx.x * blockDim.x + threadIdx.x;
    if (n < N_NODES) {
        float dg = g_deg[n];
        g_dis[n] = (dg > 0.f) ? rsqrtf(dg) : 0.f;
    }
}

// Single-block exclusive scan of rowcnt -> rowptr (and rowfill copy)
__global__ void scan_kernel() {
    __shared__ int sums[1024];
    int t = threadIdx.x;
    const int IT = 30;  // 1024*30 >= 30000
    int base = t * IT;
    int s = 0;
    for (int i = 0; i < IT; i++) {
        int idx = base + i;
        if (idx < N_NODES) s += g_rowcnt[idx];
    }
    sums[t] = s;
    __syncthreads();
    for (int d = 1; d < 1024; d <<= 1) {
        int v = (t >= d) ? sums[t - d] : 0;
        __syncthreads();
        sums[t] += v;
        __syncthreads();
    }
    int run = sums[t] - s;  // exclusive
    for (int i = 0; i < IT; i++) {
        int idx = base + i;
        if (idx < N_NODES) {
            g_rowptr[idx] = run;
            g_rowfill[idx] = run;
            run += g_rowcnt[idx];
        }
    }
    if (t == 1023) g_rowptr[N_NODES] = sums[1023];
}

__global__ void csrfill_kernel(const int* __restrict__ ei) {
    int e = blockIdx.x * blockDim.x + threadIdx.x;
    if (e >= N_EDGES) return;
    int s = ei[e], d = ei[N_EDGES + e];
    if (s != d) {
        int pos = atomicAdd(&g_rowfill[d], 1);
        g_col[pos] = s;
        g_ew[pos] = g_dis[s] * g_dis[d];
    }
}

// Pack Wx[4][5][8][32], Wh[4][5][32][32] -> WBt[gh][kk], gh = g*32+h,
// kk<40: (k,f), kk>=40: (k,c)
__global__ void pack_wbt_kernel(const float* __restrict__ Wx,
                                const float* __restrict__ Wh) {
    int id = blockIdx.x * blockDim.x + threadIdx.x;
    if (id >= 128 * 200) return;
    int gh = id / 200, kk = id % 200;
    int g = gh >> 5, h = gh & 31;
    float w;
    if (kk < 40) {
        int k5 = kk >> 3, f = kk & 7;
        w = Wx[((g * 5 + k5) * 8 + f) * 32 + h];
    } else {
        int q = kk - 40;
        int k5 = q >> 5, c = q & 31;
        w = Wh[((g * 5 + k5) * 32 + c) * 32 + h];
    }
    g_WBt[gh * 200 + kk] = w;
}

// timesteps [T][N][F] -> TxX[0] as [N][T*F]
__global__ void xt_kernel(const float* __restrict__ ts) {
    int i = blockIdx.x * blockDim.x + threadIdx.x;
    if (i >= N_NODES * 64) return;
    int n = i >> 6, r = i & 63;
    int tt = r >> 3, f = r & 7;
    g_TxX[0][i] = ts[(tt * N_NODES + n) * 8 + f];
}

__global__ void zero_state_kernel() {
    int i = blockIdx.x * blockDim.x + threadIdx.x;
    if (i < N_NODES * 32) { g_H[i] = 0.f; g_C[i] = 0.f; }
}

// ---------------------------------------------------------------------------
// SpMM: out = alpha * lap(xin) - xprev, lap(x)[n] = -sum_{e in row n} w_e * x[col_e]
// Warp per dst node, lane = channel.
// ---------------------------------------------------------------------------
__global__ void spmm_x_kernel(int k) {
    int gtid = blockIdx.x * blockDim.x + threadIdx.x;
    int row = gtid >> 5, lane = gtid & 31;
    if (row >= N_NODES) return;
    const float* __restrict__ xin = g_TxX[k - 1];
    const float* __restrict__ xprev = (k >= 2) ? g_TxX[k - 2] : nullptr;
    float* __restrict__ xout = g_TxX[k];
    float alpha = (k >= 2) ? 2.f : 1.f;
    int e = g_rowptr[row], end = g_rowptr[row + 1];
    float a0 = 0.f, a1 = 0.f;
    for (; e + 1 < end; e += 2) {
        int s0 = g_col[e], s1 = g_col[e + 1];
        float w0 = g_ew[e], w1 = g_ew[e + 1];
        float x00 = xin[s0 * 64 + lane], x01 = xin[s0 * 64 + 32 + lane];
        float x10 = xin[s1 * 64 + lane], x11 = xin[s1 * 64 + 32 + lane];
        a0 = fmaf(w0, x00, a0); a0 = fmaf(w1, x10, a0);
        a1 = fmaf(w0, x01, a1); a1 = fmaf(w1, x11, a1);
    }
    if (e < end) {
        int s0 = g_col[e]; float w0 = g_ew[e];
        a0 = fmaf(w0, xin[s0 * 64 + lane], a0);
        a1 = fmaf(w0, xin[s0 * 64 + 32 + lane], a1);
    }
    float o0 = -alpha * a0, o1 = -alpha * a1;
    if (xprev) {
        o0 -= xprev[row * 64 + lane];
        o1 -= xprev[row * 64 + 32 + lane];
    }
    xout[row * 64 + lane] = o0;
    xout[row * 64 + 32 + lane] = o1;
}

__global__ void spmm_h_kernel(int k) {
    int gtid = blockIdx.x * blockDim.x + threadIdx.x;
    int row = gtid >> 5, lane = gtid & 31;
    if (row >= N_NODES) return;
    const float* __restrict__ xin = (k == 1) ? g_H : g_TxH[k - 2];
    const float* __restrict__ xprev = (k == 1) ? nullptr : ((k == 2) ? g_H : g_TxH[k - 3]);
    float* __restrict__ xout = g_TxH[k - 1];
    float alpha = (k == 1) ? 1.f : 2.f;
    int e = g_rowptr[row], end = g_rowptr[row + 1];
    float a0 = 0.f, a0b = 0.f;
    for (; e + 1 < end; e += 2) {
        int s0 = g_col[e], s1 = g_col[e + 1];
        float w0 = g_ew[e], w1 = g_ew[e + 1];
        a0  = fmaf(w0, xin[s0 * 32 + lane], a0);
        a0b = fmaf(w1, xin[s1 * 32 + lane], a0b);
    }
    if (e < end) {
        a0 = fmaf(g_ew[e], xin[g_col[e] * 32 + lane], a0);
    }
    float o0 = -alpha * (a0 + a0b);
    if (xprev) o0 -= xprev[row * 32 + lane];
    xout[row * 32 + lane] = o0;
}

// ---------------------------------------------------------------------------
// Gates GEMM: Z[n][128] = A(n,:,t) [200] @ WBt^T, where
//   A cols 0..39   = TxX[k][n][t*8+f]
//   A cols 40..71  = H[n][c]
//   A cols 72..199 = TxH[k-1][n][c]
// BM=64, BN=128, BK=8, 256 threads, 8x4 micro-tile, fma.rn.f32x2 k-paired.
// ---------------------------------------------------------------------------
#define FMA2(acc, a, b) \
    asm volatile("fma.rn.f32x2 %0, %1, %2, %0;" : "+l"(acc) : "l"(a), "l"(b))

__global__ __launch_bounds__(256) void gates_gemm_kernel(int t) {
    __shared__ __align__(16) float As[64 * 8];    // [m][k]
    __shared__ __align__(16) float Bs[128 * 12];  // [n][k], stride 12 (conflict-free)
    int tid = threadIdx.x;
    int cg = tid & 31, rg = tid >> 5;
    int m0 = blockIdx.x * 64;
    int t8 = t * 8;

    unsigned long long acc[8][4];
#pragma unroll
    for (int i = 0; i < 8; i++)
#pragma unroll
        for (int j = 0; j < 4; j++) acc[i][j] = 0ull;

    for (int k0 = 0; k0 < 200; k0 += 8) {
        // A tile: 512 elems, 2 per thread; consecutive threads write consecutive k
#pragma unroll
        for (int i = 0; i < 2; i++) {
            int l = tid + i * 256;
            int ml = l >> 3, kl = l & 7;
            int kk = k0 + kl, n = m0 + ml;
            float v = 0.f;
            if (n < N_NODES) {
                if (kk < 40) {
                    int k5 = kk >> 3, f = kk & 7;
                    v = g_TxX[k5][n * 64 + t8 + f];
                } else if (kk < 72) {
                    v = g_H[n * 32 + (kk - 40)];
                } else {
                    int q = kk - 72;
                    v = g_TxH[q >> 5][n * 32 + (q & 31)];
                }
            }
            As[ml * 8 + kl] = v;
        }
        // B tile: 1024 elems as float4
        {
            int nl = tid >> 1, kl4 = (tid & 1) * 4;
            float4 wv = *(const float4*)&g_WBt[nl * 200 + k0 + kl4];
            *(float4*)&Bs[nl * 12 + kl4] = wv;
        }
        __syncthreads();
#pragma unroll
        for (int kc = 0; kc < 8; kc += 4) {
            unsigned long long b0[4], b1[4];
#pragma unroll
            for (int j = 0; j < 4; j++) {
                ulonglong2 bv = *(const ulonglong2*)&Bs[(cg + 32 * j) * 12 + kc];
                b0[j] = bv.x; b1[j] = bv.y;
            }
#pragma unroll
            for (int i = 0; i < 8; i++) {
                ulonglong2 av = *(const ulonglong2*)&As[(rg * 8 + i) * 8 + kc];
#pragma unroll
                for (int j = 0; j < 4; j++) {
                    FMA2(acc[i][j], av.x, b0[j]);
                    FMA2(acc[i][j], av.y, b1[j]);
                }
            }
        }
        __syncthreads();
    }
#pragma unroll
    for (int i = 0; i < 8; i++) {
        int n = m0 + rg * 8 + i;
        if (n < N_NODES) {
#pragma unroll
            for (int j = 0; j < 4; j++) {
                union { unsigned long long u; float2 f; } cv;
                cv.u = acc[i][j];
                g_Z[n * 128 + cg + 32 * j] = cv.f.x + cv.f.y;
            }
        }
    }
}

// ---------------------------------------------------------------------------
// LSTM pointwise update
// ---------------------------------------------------------------------------
__device__ __forceinline__ float sigm(float x) {
    return 1.f / (1.f + __expf(-x));
}

__global__ void lstm_kernel(const float* __restrict__ w_c,
                            const float* __restrict__ b) {
    int g = blockIdx.x * blockDim.x + threadIdx.x;
    if (g >= N_NODES * 32) return;
    int n = g >> 5, h = g & 31;
    float zi = g_Z[n * 128 + h];
    float zf = g_Z[n * 128 + 32 + h];
    float zc = g_Z[n * 128 + 64 + h];
    float zo = g_Z[n * 128 + 96 + h];
    float c = g_C[g];
    float I  = sigm(zi + w_c[h] * c + b[h]);
    float Fg = sigm(zf + w_c[32 + h] * c + b[32 + h]);
    float T  = tanhf(zc + b[64 + h]);
    float cn = Fg * c + I * T;
    float O  = sigm(zo + w_c[64 + h] * cn + b[96 + h]);
    g_C[g] = cn;
    g_H[g] = O * tanhf(cn);
}

// ---------------------------------------------------------------------------
// Output head: out[n][p] = relu(H[n]) . W_lin[p] + b_lin[p]
// ---------------------------------------------------------------------------
__global__ void head_kernel(const float* __restrict__ Wl,
                            const float* __restrict__ bl,
                            float* __restrict__ out) {
    __shared__ float w[256];
    __shared__ float b[8];
    int tid = threadIdx.x;
    if (tid < 256) w[tid] = Wl[tid];
    if (tid < 8) b[tid] = bl[tid];
    __syncthreads();
    int n = blockIdx.x * blockDim.x + tid;
    if (n >= N_NODES) return;
    float h[32];
#pragma unroll
    for (int c = 0; c < 32; c++) {
        float v = g_H[n * 32 + c];
        h[c] = v > 0.f ? v : 0.f;
    }
#pragma unroll
    for (int p = 0; p < 8; p++) {
        float a = b[p];
#pragma unroll
        for (int c = 0; c < 32; c++) a = fmaf(h[c], w[p * 32 + c], a);
        out[n * 8 + p] = a;
    }
}

// ---------------------------------------------------------------------------
// kernel_launch
// ---------------------------------------------------------------------------
extern "C" void kernel_launch(void* const* d_in, const int* in_sizes, int n_in,
                              void* d_out, int out_size) {
    const float* timesteps = (const float*)d_in[0];
    const int*   edge_idx  = (const int*)d_in[1];
    const float* Wx        = (const float*)d_in[2];
    const float* Wh        = (const float*)d_in[3];
    const float* w_c       = (const float*)d_in[4];
    const float* b_gates   = (const float*)d_in[5];
    const float* W_lin     = (const float*)d_in[6];
    const float* b_lin     = (const float*)d_in[7];
    float* out = (float*)d_out;

    const int TB = 256;
    const int gN   = (N_NODES + TB - 1) / TB;
    const int gE   = (N_EDGES + TB - 1) / TB;
    const int gNC  = (N_NODES * 32 + TB - 1) / TB;
    const int gX   = (N_NODES * 64 + TB - 1) / TB;
    const int gSp  = (N_NODES * 32 + TB - 1) / TB;  // warp per node, 8 nodes/block
    const int gGm  = (N_NODES + 63) / 64;
    const int gPk  = (128 * 200 + TB - 1) / TB;

    // Graph structure + normalization
    zero_prep_kernel<<<gN, TB>>>();
    hist_kernel<<<gE, TB>>>(edge_idx);
    dis_kernel<<<gN, TB>>>();
    scan_kernel<<<1, 1024>>>();
    csrfill_kernel<<<gE, TB>>>(edge_idx);

    // Weight pack + X Chebyshev polys (all timesteps at once, C=64)
    pack_wbt_kernel<<<gPk, TB>>>(Wx, Wh);
    xt_kernel<<<gX, TB>>>(timesteps);
    for (int k = 1; k <= 4; k++) spmm_x_kernel<<<gSp, TB>>>(k);

    // LSTM state
    zero_state_kernel<<<gNC, TB>>>();

    for (int t = 0; t < T_STEPS; t++) {
        for (int k = 1; k <= 4; k++) spmm_h_kernel<<<gSp, TB>>>(k);
        gates_gemm_kernel<<<gGm, 256>>>(t);
        lstm_kernel<<<gNC, TB>>>(w_c, b_gates);
    }

    head_kernel<<<gN, TB>>>(W_lin, b_lin, out);
}

// round 8
// speedup vs baseline: 1.0052x; 1.0014x over previous
#include <cuda_runtime.h>
#include <cuda_bf16.h>

// Problem constants (fixed by the dataset)
#define N_NODES 30000
#define N_EDGES 480000
#define T_STEPS 8
#define F_IN 8
#define HID 32
#define KCHEB 5
#define PERIODS 8

// ---------------------------------------------------------------------------
// Scratch (device globals; allocation-free rule)
// ---------------------------------------------------------------------------
__device__ float g_deg[N_NODES];
__device__ float g_dis[N_NODES];
__device__ int   g_rowcnt[N_NODES];
__device__ int   g_rowptr[N_NODES + 1];
__device__ int   g_rowfill[N_NODES];
__device__ int   g_col[N_EDGES];
__device__ float g_ew[N_EDGES];

// Chebyshev polys of X: [k][n][t*8+f], k=0..4, C=64
__device__ float g_TxX[5][N_NODES * 64];
// Chebyshev polys of H for k=1..4: [k-1][n][c], C=32
__device__ float g_TxH[4][N_NODES * 32];
__device__ float g_H[N_NODES * 32];
__device__ float g_C[N_NODES * 32];
__device__ float g_Z[N_NODES * 128];       // gate pre-activations [n][4*32]
__device__ float g_WBt[128 * 200];         // packed weights, [gate-out gh][k-dim kk]

// ---------------------------------------------------------------------------
// Prep kernels
// ---------------------------------------------------------------------------
__global__ void zero_prep_kernel() {
    int n = blockIdx.x * blockDim.x + threadIdx.x;
    if (n < N_NODES) { g_deg[n] = 0.f; g_rowcnt[n] = 0; }
}

__global__ void hist_kernel(const int* __restrict__ ei) {
    int e = blockIdx.x * blockDim.x + threadIdx.x;
    if (e >= N_EDGES) return;
    int s = ei[e], d = ei[N_EDGES + e];
    if (s != d) {
        atomicAdd(&g_deg[s], 1.f);
        atomicAdd(&g_rowcnt[d], 1);
    }
}

__global__ void dis_kernel() {
    int n = blockIdx.x * blockDim.x + threadIdx.x;
    if (n < N_NODES) {
        float dg = g_deg[n];
        g_dis[n] = (dg > 0.f) ? rsqrtf(dg) : 0.f;
    }
}

// Single-block exclusive scan of rowcnt -> rowptr (and rowfill copy)
__global__ void scan_kernel() {
    __shared__ int sums[1024];
    int t = threadIdx.x;
    const int IT = 30;  // 1024*30 >= 30000
    int base = t * IT;
    int s = 0;
    for (int i = 0; i < IT; i++) {
        int idx = base + i;
        if (idx < N_NODES) s += g_rowcnt[idx];
    }
    sums[t] = s;
    __syncthreads();
    for (int d = 1; d < 1024; d <<= 1) {
        int v = (t >= d) ? sums[t - d] : 0;
        __syncthreads();
        sums[t] += v;
        __syncthreads();
    }
    int run = sums[t] - s;  // exclusive
    for (int i = 0; i < IT; i++) {
        int idx = base + i;
        if (idx < N_NODES) {
            g_rowptr[idx] = run;
            g_rowfill[idx] = run;
            run += g_rowcnt[idx];
        }
    }
    if (t == 1023) g_rowptr[N_NODES] = sums[1023];
}

__global__ void csrfill_kernel(const int* __restrict__ ei) {
    int e = blockIdx.x * blockDim.x + threadIdx.x;
    if (e >= N_EDGES) return;
    int s = ei[e], d = ei[N_EDGES + e];
    if (s != d) {
        int pos = atomicAdd(&g_rowfill[d], 1);
        g_col[pos] = s;
        g_ew[pos] = g_dis[s] * g_dis[d];
    }
}

// Pack Wx[4][5][8][32], Wh[4][5][32][32] -> WBt[gh][kk], gh = g*32+h,
// kk<40: (k,f), kk>=40: (k,c)
__global__ void pack_wbt_kernel(const float* __restrict__ Wx,
                                const float* __restrict__ Wh) {
    int id = blockIdx.x * blockDim.x + threadIdx.x;
    if (id >= 128 * 200) return;
    int gh = id / 200, kk = id % 200;
    int g = gh >> 5, h = gh & 31;
    float w;
    if (kk < 40) {
        int k5 = kk >> 3, f = kk & 7;
        w = Wx[((g * 5 + k5) * 8 + f) * 32 + h];
    } else {
        int q = kk - 40;
        int k5 = q >> 5, c = q & 31;
        w = Wh[((g * 5 + k5) * 32 + c) * 32 + h];
    }
    g_WBt[gh * 200 + kk] = w;
}

// timesteps [T][N][F] -> TxX[0] as [N][T*F]
__global__ void xt_kernel(const float* __restrict__ ts) {
    int i = blockIdx.x * blockDim.x + threadIdx.x;
    if (i >= N_NODES * 64) return;
    int n = i >> 6, r = i & 63;
    int tt = r >> 3, f = r & 7;
    g_TxX[0][i] = ts[(tt * N_NODES + n) * 8 + f];
}

__global__ void zero_state_kernel() {
    int i = blockIdx.x * blockDim.x + threadIdx.x;
    if (i < N_NODES * 32) { g_H[i] = 0.f; g_C[i] = 0.f; }
}

// ---------------------------------------------------------------------------
// SpMM: out = alpha * lap(xin) - xprev, lap(x)[n] = -sum_{e in row n} w_e * x[col_e]
// Warp per dst node, lane = channel.
// ---------------------------------------------------------------------------
__global__ void spmm_x_kernel(int k) {
    int gtid = blockIdx.x * blockDim.x + threadIdx.x;
    int row = gtid >> 5, lane = gtid & 31;
    if (row >= N_NODES) return;
    const float* __restrict__ xin = g_TxX[k - 1];
    const float* __restrict__ xprev = (k >= 2) ? g_TxX[k - 2] : nullptr;
    float* __restrict__ xout = g_TxX[k];
    float alpha = (k >= 2) ? 2.f : 1.f;
    int e = g_rowptr[row], end = g_rowptr[row + 1];
    float a0 = 0.f, a1 = 0.f;
    for (; e + 1 < end; e += 2) {
        int s0 = g_col[e], s1 = g_col[e + 1];
        float w0 = g_ew[e], w1 = g_ew[e + 1];
        float x00 = xin[s0 * 64 + lane], x01 = xin[s0 * 64 + 32 + lane];
        float x10 = xin[s1 * 64 + lane], x11 = xin[s1 * 64 + 32 + lane];
        a0 = fmaf(w0, x00, a0); a0 = fmaf(w1, x10, a0);
        a1 = fmaf(w0, x01, a1); a1 = fmaf(w1, x11, a1);
    }
    if (e < end) {
        int s0 = g_col[e]; float w0 = g_ew[e];
        a0 = fmaf(w0, xin[s0 * 64 + lane], a0);
        a1 = fmaf(w0, xin[s0 * 64 + 32 + lane], a1);
    }
    float o0 = -alpha * a0, o1 = -alpha * a1;
    if (xprev) {
        o0 -= xprev[row * 64 + lane];
        o1 -= xprev[row * 64 + 32 + lane];
    }
    xout[row * 64 + lane] = o0;
    xout[row * 64 + 32 + lane] = o1;
}

__global__ void spmm_h_kernel(int k) {
    int gtid = blockIdx.x * blockDim.x + threadIdx.x;
    int row = gtid >> 5, lane = gtid & 31;
    if (row >= N_NODES) return;
    const float* __restrict__ xin = (k == 1) ? g_H : g_TxH[k - 2];
    const float* __restrict__ xprev = (k == 1) ? nullptr : ((k == 2) ? g_H : g_TxH[k - 3]);
    float* __restrict__ xout = g_TxH[k - 1];
    float alpha = (k == 1) ? 1.f : 2.f;
    int e = g_rowptr[row], end = g_rowptr[row + 1];
    float a0 = 0.f, a0b = 0.f;
    for (; e + 1 < end; e += 2) {
        int s0 = g_col[e], s1 = g_col[e + 1];
        float w0 = g_ew[e], w1 = g_ew[e + 1];
        a0  = fmaf(w0, xin[s0 * 32 + lane], a0);
        a0b = fmaf(w1, xin[s1 * 32 + lane], a0b);
    }
    if (e < end) {
        a0 = fmaf(g_ew[e], xin[g_col[e] * 32 + lane], a0);
    }
    float o0 = -alpha * (a0 + a0b);
    if (xprev) o0 -= xprev[row * 32 + lane];
    xout[row * 32 + lane] = o0;
}

// ---------------------------------------------------------------------------
// Gates GEMM: Z[n][128] = A(n,:,t) [200] @ WBt^T, where
//   A cols 0..39   = TxX[k][n][t*8+f]
//   A cols 40..71  = H[n][c]
//   A cols 72..199 = TxH[k-1][n][c]
// BM=64, BN=128, BK=8, 256 threads, 8x4 micro-tile, fma.rn.f32x2 k-paired.
// ---------------------------------------------------------------------------
#define FMA2(acc, a, b) \
    asm volatile("fma.rn.f32x2 %0, %1, %2, %0;" : "+l"(acc) : "l"(a), "l"(b))

__global__ __launch_bounds__(256) void gates_gemm_kernel(int t) {
    __shared__ __align__(16) float As[64 * 8];    // [m][k]
    __shared__ __align__(16) float Bs[128 * 12];  // [n][k], stride 12 (conflict-free)
    int tid = threadIdx.x;
    int cg = tid & 31, rg = tid >> 5;
    int m0 = blockIdx.x * 64;
    int t8 = t * 8;

    unsigned long long acc[8][4];
#pragma unroll
    for (int i = 0; i < 8; i++)
#pragma unroll
        for (int j = 0; j < 4; j++) acc[i][j] = 0ull;

    for (int k0 = 0; k0 < 200; k0 += 8) {
        // A tile: 512 elems, 2 per thread; consecutive threads write consecutive k
#pragma unroll
        for (int i = 0; i < 2; i++) {
            int l = tid + i * 256;
            int ml = l >> 3, kl = l & 7;
            int kk = k0 + kl, n = m0 + ml;
            float v = 0.f;
            if (n < N_NODES) {
                if (kk < 40) {
                    int k5 = kk >> 3, f = kk & 7;
                    v = g_TxX[k5][n * 64 + t8 + f];
                } else if (kk < 72) {
                    v = g_H[n * 32 + (kk - 40)];
                } else {
                    int q = kk - 72;
                    v = g_TxH[q >> 5][n * 32 + (q & 31)];
                }
            }
            As[ml * 8 + kl] = v;
        }
        // B tile: 1024 elems as float4
        {
            int nl = tid >> 1, kl4 = (tid & 1) * 4;
            float4 wv = *(const float4*)&g_WBt[nl * 200 + k0 + kl4];
            *(float4*)&Bs[nl * 12 + kl4] = wv;
        }
        __syncthreads();
#pragma unroll
        for (int kc = 0; kc < 8; kc += 4) {
            unsigned long long b0[4], b1[4];
#pragma unroll
            for (int j = 0; j < 4; j++) {
                ulonglong2 bv = *(const ulonglong2*)&Bs[(cg + 32 * j) * 12 + kc];
                b0[j] = bv.x; b1[j] = bv.y;
            }
#pragma unroll
            for (int i = 0; i < 8; i++) {
                ulonglong2 av = *(const ulonglong2*)&As[(rg * 8 + i) * 8 + kc];
#pragma unroll
                for (int j = 0; j < 4; j++) {
                    FMA2(acc[i][j], av.x, b0[j]);
                    FMA2(acc[i][j], av.y, b1[j]);
                }
            }
        }
        __syncthreads();
    }
#pragma unroll
    for (int i = 0; i < 8; i++) {
        int n = m0 + rg * 8 + i;
        if (n < N_NODES) {
#pragma unroll
            for (int j = 0; j < 4; j++) {
                union { unsigned long long u; float2 f; } cv;
                cv.u = acc[i][j];
                g_Z[n * 128 + cg + 32 * j] = cv.f.x + cv.f.y;
            }
        }
    }
}

// ---------------------------------------------------------------------------
// LSTM pointwise update
// ---------------------------------------------------------------------------
__device__ __forceinline__ float sigm(float x) {
    return 1.f / (1.f + __expf(-x));
}

__global__ void lstm_kernel(const float* __restrict__ w_c,
                            const float* __restrict__ b) {
    int g = blockIdx.x * blockDim.x + threadIdx.x;
    if (g >= N_NODES * 32) return;
    int n = g >> 5, h = g & 31;
    float zi = g_Z[n * 128 + h];
    float zf = g_Z[n * 128 + 32 + h];
    float zc = g_Z[n * 128 + 64 + h];
    float zo = g_Z[n * 128 + 96 + h];
    float c = g_C[g];
    float I  = sigm(zi + w_c[h] * c + b[h]);
    float Fg = sigm(zf + w_c[32 + h] * c + b[32 + h]);
    float T  = tanhf(zc + b[64 + h]);
    float cn = Fg * c + I * T;
    float O  = sigm(zo + w_c[64 + h] * cn + b[96 + h]);
    g_C[g] = cn;
    g_H[g] = O * tanhf(cn);
}

// ---------------------------------------------------------------------------
// Output head: out[n][p] = relu(H[n]) . W_lin[p] + b_lin[p]
// ---------------------------------------------------------------------------
__global__ void head_kernel(const float* __restrict__ Wl,
                            const float* __restrict__ bl,
                            float* __restrict__ out) {
    __shared__ float w[256];
    __shared__ float b[8];
    int tid = threadIdx.x;
    if (tid < 256) w[tid] = Wl[tid];
    if (tid < 8) b[tid] = bl[tid];
    __syncthreads();
    int n = blockIdx.x * blockDim.x + tid;
    if (n >= N_NODES) return;
    float h[32];
#pragma unroll
    for (int c = 0; c < 32; c++) {
        float v = g_H[n * 32 + c];
        h[c] = v > 0.f ? v : 0.f;
    }
#pragma unroll
    for (int p = 0; p < 8; p++) {
        float a = b[p];
#pragma unroll
        for (int c = 0; c < 32; c++) a = fmaf(h[c], w[p * 32 + c], a);
        out[n * 8 + p] = a;
    }
}

// ---------------------------------------------------------------------------
// kernel_launch
// ---------------------------------------------------------------------------
extern "C" void kernel_launch(void* const* d_in, const int* in_sizes, int n_in,
                              void* d_out, int out_size) {
    const float* timesteps = (const float*)d_in[0];
    const int*   edge_idx  = (const int*)d_in[1];
    const float* Wx        = (const float*)d_in[2];
    const float* Wh        = (const float*)d_in[3];
    const float* w_c       = (const float*)d_in[4];
    const float* b_gates   = (const float*)d_in[5];
    const float* W_lin     = (const float*)d_in[6];
    const float* b_lin     = (const float*)d_in[7];
    float* out = (float*)d_out;

    const int TB = 256;
    const int gN   = (N_NODES + TB - 1) / TB;
    const int gE   = (N_EDGES + TB - 1) / TB;
    const int gNC  = (N_NODES * 32 + TB - 1) / TB;
    const int gX   = (N_NODES * 64 + TB - 1) / TB;
    const int gSp  = (N_NODES * 32 + TB - 1) / TB;  // warp per node, 8 nodes/block
    const int gGm  = (N_NODES + 63) / 64;
    const int gPk  = (128 * 200 + TB - 1) / TB;

    // Graph structure + normalization
    zero_prep_kernel<<<gN, TB>>>();
    hist_kernel<<<gE, TB>>>(edge_idx);
    dis_kernel<<<gN, TB>>>();
    scan_kernel<<<1, 1024>>>();
    csrfill_kernel<<<gE, TB>>>(edge_idx);

    // Weight pack + X Chebyshev polys (all timesteps at once, C=64)
    pack_wbt_kernel<<<gPk, TB>>>(Wx, Wh);
    xt_kernel<<<gX, TB>>>(timesteps);
    for (int k = 1; k <= 4; k++) spmm_x_kernel<<<gSp, TB>>>(k);

    // LSTM state
    zero_state_kernel<<<gNC, TB>>>();

    for (int t = 0; t < T_STEPS; t++) {
        for (int k = 1; k <= 4; k++) spmm_h_kernel<<<gSp, TB>>>(k);
        gates_gemm_kernel<<<gGm, 256>>>(t);
        lstm_kernel<<<gNC, TB>>>(w_c, b_gates);
    }

    head_kernel<<<gN, TB>>>(W_lin, b_lin, out);
}

// round 9
// speedup vs baseline: 1.0080x; 1.0028x over previous
#include <cuda_runtime.h>
#include <cuda_bf16.h>

// Problem constants (fixed by the dataset)
#define N_NODES 30000
#define N_EDGES 480000
#define T_STEPS 8
#define F_IN 8
#define HID 32
#define KCHEB 5
#define PERIODS 8

// ---------------------------------------------------------------------------
// Scratch (device globals; allocation-free rule)
// ---------------------------------------------------------------------------
__device__ float g_deg[N_NODES];
__device__ float g_dis[N_NODES];
__device__ int   g_rowcnt[N_NODES];
__device__ int   g_rowptr[N_NODES + 1];
__device__ int   g_rowfill[N_NODES];
__device__ int   g_col[N_EDGES];
__device__ float g_ew[N_EDGES];

// Chebyshev polys of X: [k][n][t*8+f], k=0..4, C=64
__device__ float g_TxX[5][N_NODES * 64];
// Chebyshev polys of H for k=1..4: [k-1][n][c], C=32
__device__ float g_TxH[4][N_NODES * 32];
__device__ float g_H[N_NODES * 32];
__device__ float g_C[N_NODES * 32];
__device__ float g_Z[N_NODES * 128];       // gate pre-activations [n][4*32]
__device__ float g_WBt[128 * 200];         // packed weights, [gate-out gh][k-dim kk]

// ---------------------------------------------------------------------------
// Prep kernels
// ---------------------------------------------------------------------------
__global__ void zero_prep_kernel() {
    int n = blockIdx.x * blockDim.x + threadIdx.x;
    if (n < N_NODES) { g_deg[n] = 0.f; g_rowcnt[n] = 0; }
}

__global__ void hist_kernel(const int* __restrict__ ei) {
    int e = blockIdx.x * blockDim.x + threadIdx.x;
    if (e >= N_EDGES) return;
    int s = ei[e], d = ei[N_EDGES + e];
    if (s != d) {
        atomicAdd(&g_deg[s], 1.f);
        atomicAdd(&g_rowcnt[d], 1);
    }
}

__global__ void dis_kernel() {
    int n = blockIdx.x * blockDim.x + threadIdx.x;
    if (n < N_NODES) {
        float dg = g_deg[n];
        g_dis[n] = (dg > 0.f) ? rsqrtf(dg) : 0.f;
    }
}

// Single-block exclusive scan of rowcnt -> rowptr (and rowfill copy)
__global__ void scan_kernel() {
    __shared__ int sums[1024];
    int t = threadIdx.x;
    const int IT = 30;  // 1024*30 >= 30000
    int base = t * IT;
    int s = 0;
    for (int i = 0; i < IT; i++) {
        int idx = base + i;
        if (idx < N_NODES) s += g_rowcnt[idx];
    }
    sums[t] = s;
    __syncthreads();
    for (int d = 1; d < 1024; d <<= 1) {
        int v = (t >= d) ? sums[t - d] : 0;
        __syncthreads();
        sums[t] += v;
        __syncthreads();
    }
    int run = sums[t] - s;  // exclusive
    for (int i = 0; i < IT; i++) {
        int idx = base + i;
        if (idx < N_NODES) {
            g_rowptr[idx] = run;
            g_rowfill[idx] = run;
            run += g_rowcnt[idx];
        }
    }
    if (t == 1023) g_rowptr[N_NODES] = sums[1023];
}

__global__ void csrfill_kernel(const int* __restrict__ ei) {
    int e = blockIdx.x * blockDim.x + threadIdx.x;
    if (e >= N_EDGES) return;
    int s = ei[e], d = ei[N_EDGES + e];
    if (s != d) {
        int pos = atomicAdd(&g_rowfill[d], 1);
        g_col[pos] = s;
        g_ew[pos] = g_dis[s] * g_dis[d];
    }
}

// Pack Wx[4][5][8][32], Wh[4][5][32][32] -> WBt[gh][kk], gh = g*32+h,
// kk<40: (k,f), kk>=40: (k,c)
__global__ void pack_wbt_kernel(const float* __restrict__ Wx,
                                const float* __restrict__ Wh) {
    int id = blockIdx.x * blockDim.x + threadIdx.x;
    if (id >= 128 * 200) return;
    int gh = id / 200, kk = id % 200;
    int g = gh >> 5, h = gh & 31;
    float w;
    if (kk < 40) {
        int k5 = kk >> 3, f = kk & 7;
        w = Wx[((g * 5 + k5) * 8 + f) * 32 + h];
    } else {
        int q = kk - 40;
        int k5 = q >> 5, c = q & 31;
        w = Wh[((g * 5 + k5) * 32 + c) * 32 + h];
    }
    g_WBt[gh * 200 + kk] = w;
}

// timesteps [T][N][F] -> TxX[0] as [N][T*F]
__global__ void xt_kernel(const float* __restrict__ ts) {
    int i = blockIdx.x * blockDim.x + threadIdx.x;
    if (i >= N_NODES * 64) return;
    int n = i >> 6, r = i & 63;
    int tt = r >> 3, f = r & 7;
    g_TxX[0][i] = ts[(tt * N_NODES + n) * 8 + f];
}

__global__ void zero_state_kernel() {
    int i = blockIdx.x * blockDim.x + threadIdx.x;
    if (i < N_NODES * 32) { g_H[i] = 0.f; g_C[i] = 0.f; }
}

// ---------------------------------------------------------------------------
// SpMM: out = alpha * lap(xin) - xprev, lap(x)[n] = -sum_{e in row n} w_e * x[col_e]
// Warp per dst node, lane = channel.
// ---------------------------------------------------------------------------
__global__ void spmm_x_kernel(int k) {
    int gtid = blockIdx.x * blockDim.x + threadIdx.x;
    int row = gtid >> 5, lane = gtid & 31;
    if (row >= N_NODES) return;
    const float* __restrict__ xin = g_TxX[k - 1];
    const float* __restrict__ xprev = (k >= 2) ? g_TxX[k - 2] : nullptr;
    float* __restrict__ xout = g_TxX[k];
    float alpha = (k >= 2) ? 2.f : 1.f;
    int e = g_rowptr[row], end = g_rowptr[row + 1];
    float a0 = 0.f, a1 = 0.f;
    for (; e + 1 < end; e += 2) {
        int s0 = g_col[e], s1 = g_col[e + 1];
        float w0 = g_ew[e], w1 = g_ew[e + 1];
        float x00 = xin[s0 * 64 + lane], x01 = xin[s0 * 64 + 32 + lane];
        float x10 = xin[s1 * 64 + lane], x11 = xin[s1 * 64 + 32 + lane];
        a0 = fmaf(w0, x00, a0); a0 = fmaf(w1, x10, a0);
        a1 = fmaf(w0, x01, a1); a1 = fmaf(w1, x11, a1);
    }
    if (e < end) {
        int s0 = g_col[e]; float w0 = g_ew[e];
        a0 = fmaf(w0, xin[s0 * 64 + lane], a0);
        a1 = fmaf(w0, xin[s0 * 64 + 32 + lane], a1);
    }
    float o0 = -alpha * a0, o1 = -alpha * a1;
    if (xprev) {
        o0 -= xprev[row * 64 + lane];
        o1 -= xprev[row * 64 + 32 + lane];
    }
    xout[row * 64 + lane] = o0;
    xout[row * 64 + 32 + lane] = o1;
}

__global__ void spmm_h_kernel(int k) {
    int gtid = blockIdx.x * blockDim.x + threadIdx.x;
    int row = gtid >> 5, lane = gtid & 31;
    if (row >= N_NODES) return;
    const float* __restrict__ xin = (k == 1) ? g_H : g_TxH[k - 2];
    const float* __restrict__ xprev = (k == 1) ? nullptr : ((k == 2) ? g_H : g_TxH[k - 3]);
    float* __restrict__ xout = g_TxH[k - 1];
    float alpha = (k == 1) ? 1.f : 2.f;
    int e = g_rowptr[row], end = g_rowptr[row + 1];
    float a0 = 0.f, a0b = 0.f;
    for (; e + 1 < end; e += 2) {
        int s0 = g_col[e], s1 = g_col[e + 1];
        float w0 = g_ew[e], w1 = g_ew[e + 1];
        a0  = fmaf(w0, xin[s0 * 32 + lane], a0);
        a0b = fmaf(w1, xin[s1 * 32 + lane], a0b);
    }
    if (e < end) {
        a0 = fmaf(g_ew[e], xin[g_col[e] * 32 + lane], a0);
    }
    float o0 = -alpha * (a0 + a0b);
    if (xprev) o0 -= xprev[row * 32 + lane];
    xout[row * 32 + lane] = o0;
}

// ---------------------------------------------------------------------------
// Gates GEMM: Z[n][128] = A(n,:,t) [200] @ WBt^T, where
//   A cols 0..39   = TxX[k][n][t*8+f]
//   A cols 40..71  = H[n][c]
//   A cols 72..199 = TxH[k-1][n][c]
// BM=64, BN=128, BK=8, 256 threads, 8x4 micro-tile, fma.rn.f32x2 k-paired.
// ---------------------------------------------------------------------------
#define FMA2(acc, a, b) \
    asm volatile("fma.rn.f32x2 %0, %1, %2, %0;" : "+l"(acc) : "l"(a), "l"(b))

__global__ __launch_bounds__(256) void gates_gemm_kernel(int t) {
    __shared__ __align__(16) float As[64 * 8];    // [m][k]
    __shared__ __align__(16) float Bs[128 * 12];  // [n][k], stride 12 (conflict-free)
    int tid = threadIdx.x;
    int cg = tid & 31, rg = tid >> 5;
    int m0 = blockIdx.x * 64;
    int t8 = t * 8;

    unsigned long long acc[8][4];
#pragma unroll
    for (int i = 0; i < 8; i++)
#pragma unroll
        for (int j = 0; j < 4; j++) acc[i][j] = 0ull;

    for (int k0 = 0; k0 < 200; k0 += 8) {
        // A tile: 512 elems, 2 per thread; consecutive threads write consecutive k
#pragma unroll
        for (int i = 0; i < 2; i++) {
            int l = tid + i * 256;
            int ml = l >> 3, kl = l & 7;
            int kk = k0 + kl, n = m0 + ml;
            float v = 0.f;
            if (n < N_NODES) {
                if (kk < 40) {
                    int k5 = kk >> 3, f = kk & 7;
                    v = g_TxX[k5][n * 64 + t8 + f];
                } else if (kk < 72) {
                    v = g_H[n * 32 + (kk - 40)];
                } else {
                    int q = kk - 72;
                    v = g_TxH[q >> 5][n * 32 + (q & 31)];
                }
            }
            As[ml * 8 + kl] = v;
        }
        // B tile: 1024 elems as float4
        {
            int nl = tid >> 1, kl4 = (tid & 1) * 4;
            float4 wv = *(const float4*)&g_WBt[nl * 200 + k0 + kl4];
            *(float4*)&Bs[nl * 12 + kl4] = wv;
        }
        __syncthreads();
#pragma unroll
        for (int kc = 0; kc < 8; kc += 4) {
            unsigned long long b0[4], b1[4];
#pragma unroll
            for (int j = 0; j < 4; j++) {
                ulonglong2 bv = *(const ulonglong2*)&Bs[(cg + 32 * j) * 12 + kc];
                b0[j] = bv.x; b1[j] = bv.y;
            }
#pragma unroll
            for (int i = 0; i < 8; i++) {
                ulonglong2 av = *(const ulonglong2*)&As[(rg * 8 + i) * 8 + kc];
#pragma unroll
                for (int j = 0; j < 4; j++) {
                    FMA2(acc[i][j], av.x, b0[j]);
                    FMA2(acc[i][j], av.y, b1[j]);
                }
            }
        }
        __syncthreads();
    }
#pragma unroll
    for (int i = 0; i < 8; i++) {
        int n = m0 + rg * 8 + i;
        if (n < N_NODES) {
#pragma unroll
            for (int j = 0; j < 4; j++) {
                union { unsigned long long u; float2 f; } cv;
                cv.u = acc[i][j];
                g_Z[n * 128 + cg + 32 * j] = cv.f.x + cv.f.y;
            }
        }
    }
}

// ---------------------------------------------------------------------------
// LSTM pointwise update
// ---------------------------------------------------------------------------
__device__ __forceinline__ float sigm(float x) {
    return 1.f / (1.f + __expf(-x));
}

__global__ void lstm_kernel(const float* __restrict__ w_c,
                            const float* __restrict__ b) {
    int g = blockIdx.x * blockDim.x + threadIdx.x;
    if (g >= N_NODES * 32) return;
    int n = g >> 5, h = g & 31;
    float zi = g_Z[n * 128 + h];
    float zf = g_Z[n * 128 + 32 + h];
    float zc = g_Z[n * 128 + 64 + h];
    float zo = g_Z[n * 128 + 96 + h];
    float c = g_C[g];
    float I  = sigm(zi + w_c[h] * c + b[h]);
    float Fg = sigm(zf + w_c[32 + h] * c + b[32 + h]);
    float T  = tanhf(zc + b[64 + h]);
    float cn = Fg * c + I * T;
    float O  = sigm(zo + w_c[64 + h] * cn + b[96 + h]);
    g_C[g] = cn;
    g_H[g] = O * tanhf(cn);
}

// ---------------------------------------------------------------------------
// Output head: out[n][p] = relu(H[n]) . W_lin[p] + b_lin[p]
// ---------------------------------------------------------------------------
__global__ void head_kernel(const float* __restrict__ Wl,
                            const float* __restrict__ bl,
                            float* __restrict__ out) {
    __shared__ float w[256];
    __shared__ float b[8];
    int tid = threadIdx.x;
    if (tid < 256) w[tid] = Wl[tid];
    if (tid < 8) b[tid] = bl[tid];
    __syncthreads();
    int n = blockIdx.x * blockDim.x + tid;
    if (n >= N_NODES) return;
    float h[32];
#pragma unroll
    for (int c = 0; c < 32; c++) {
        float v = g_H[n * 32 + c];
        h[c] = v > 0.f ? v : 0.f;
    }
#pragma unroll
    for (int p = 0; p < 8; p++) {
        float a = b[p];
#pragma unroll
        for (int c = 0; c < 32; c++) a = fmaf(h[c], w[p * 32 + c], a);
        out[n * 8 + p] = a;
    }
}

// ---------------------------------------------------------------------------
// kernel_launch
// ---------------------------------------------------------------------------
extern "C" void kernel_launch(void* const* d_in, const int* in_sizes, int n_in,
                              void* d_out, int out_size) {
    const float* timesteps = (const float*)d_in[0];
    const int*   edge_idx  = (const int*)d_in[1];
    const float* Wx        = (const float*)d_in[2];
    const float* Wh        = (const float*)d_in[3];
    const float* w_c       = (const float*)d_in[4];
    const float* b_gates   = (const float*)d_in[5];
    const float* W_lin     = (const float*)d_in[6];
    const float* b_lin     = (const float*)d_in[7];
    float* out = (float*)d_out;

    const int TB = 256;
    const int gN   = (N_NODES + TB - 1) / TB;
    const int gE   = (N_EDGES + TB - 1) / TB;
    const int gNC  = (N_NODES * 32 + TB - 1) / TB;
    const int gX   = (N_NODES * 64 + TB - 1) / TB;
    const int gSp  = (N_NODES * 32 + TB - 1) / TB;  // warp per node, 8 nodes/block
    const int gGm  = (N_NODES + 63) / 64;
    const int gPk  = (128 * 200 + TB - 1) / TB;

    // Graph structure + normalization
    zero_prep_kernel<<<gN, TB>>>();
    hist_kernel<<<gE, TB>>>(edge_idx);
    dis_kernel<<<gN, TB>>>();
    scan_kernel<<<1, 1024>>>();
    csrfill_kernel<<<gE, TB>>>(edge_idx);

    // Weight pack + X Chebyshev polys (all timesteps at once, C=64)
    pack_wbt_kernel<<<gPk, TB>>>(Wx, Wh);
    xt_kernel<<<gX, TB>>>(timesteps);
    for (int k = 1; k <= 4; k++) spmm_x_kernel<<<gSp, TB>>>(k);

    // LSTM state
    zero_state_kernel<<<gNC, TB>>>();

    for (int t = 0; t < T_STEPS; t++) {
        for (int k = 1; k <= 4; k++) spmm_h_kernel<<<gSp, TB>>>(k);
        gates_gemm_kernel<<<gGm, 256>>>(t);
        lstm_kernel<<<gNC, TB>>>(w_c, b_gates);
    }

    head_kernel<<<gN, TB>>>(W_lin, b_lin, out);
}